// round 15
// baseline (speedup 1.0000x reference)
#include <cuda_runtime.h>
#include <math.h>

// ContextWindow: out[b, t, c*11 + i] = x[b, t+i-5, c] (zero pad in t),
// masked by t < round(2000 * lengths[b]).
// x: [32, 2000, 80] f32, lengths: [32] f32, out: [32, 2000, 880] f32.

#define B_    32
#define T_    2000
#define C_    80
#define C4_   20              // float4 per x row
#define CTX_  11
#define TT_   32              // t-rows per block
#define SROWS (TT_ + 10)      // 42 smem rows
#define SPAD  84              // 16B-aligned rows; bank key (20i+c)%32: ~2-way
#define SPAD4 21              // SPAD / 4
#define TILES 63              // ceil(2000/32)
#define J4_   (C_ * CTX_ / 4) // 220 float4 per output row
#define NTHR  224

__global__ __launch_bounds__(NTHR) void context_window_kernel(
    const float* __restrict__ x,
    const float* __restrict__ lengths,
    float* __restrict__ out)
{
    __shared__ float s[SROWS * SPAD];

    const int blk = blockIdx.x;
    const int b   = blk & 31;            // t-major: heavy (low t0) blocks first
    const int t0  = (blk >> 5) * TT_;

    // jnp.round == round-half-to-even == rintf
    const int len_abs = (int)rintf((float)T_ * lengths[b]);
    const int n_stop  = min(TT_, T_ - t0);                   // rows that exist
    const int v       = min(max(len_abs - t0, 0), n_stop);   // non-zero rows

    const int j4 = threadIdx.x;

    // ---- Fast path: fully-masked tile -> streaming zero stores only ----
    if (v <= 0) {                                            // block-uniform
        if (j4 >= J4_) return;
        float4* outp = reinterpret_cast<float4*>(out)
                     + ((size_t)b * T_ + t0) * J4_ + j4;
        const float4 z = make_float4(0.f, 0.f, 0.f, 0.f);
        int tl = 0;
#pragma unroll 1
        for (; tl + 8 <= n_stop; tl += 8) {
#pragma unroll
            for (int u = 0; u < 8; u++)
                __stcs(outp + (size_t)u * J4_, z);
            outp += (size_t)8 * J4_;
        }
#pragma unroll 1
        for (; tl < n_stop; tl++) {
            __stcs(outp, z);
            outp += J4_;
        }
        return;
    }

    // ---- Fill smem tile + halo with float4 loads ----
    {
        const int n4 = (v + 10) * C4_;                       // <= 840 float4
        const float4* __restrict__ x4 =
            reinterpret_cast<const float4*>(x) + ((size_t)b * T_ + t0 - 5) * C4_;
        float4* __restrict__ s4 = reinterpret_cast<float4*>(s);

        const bool edge = (t0 < 5) || (t0 + SROWS - 5 > T_);

#pragma unroll 1
        for (int base = threadIdx.x; base < n4; base += 4 * NTHR) {
            float4 val[4];
#pragma unroll
            for (int u = 0; u < 4; u++) {
                const int idx = base + u * NTHR;
                int ok = (idx < n4);
                if (ok && edge) {
                    const int t = t0 + idx / C4_ - 5;
                    ok = (t >= 0 && t < T_);
                }
                val[u] = make_float4(0.f, 0.f, 0.f, 0.f);
                if (ok) val[u] = x4[idx];
            }
#pragma unroll
            for (int u = 0; u < 4; u++) {
                const int idx = base + u * NTHR;
                if (idx < n4) {
                    const int r  = idx / C4_;
                    const int c4 = idx - r * C4_;
                    s4[r * SPAD4 + c4] = val[u];
                }
            }
        }
    }
    __syncthreads();

    if (j4 >= J4_) return;

    // ---- Fixed per-thread (c,i) mapping for j = 4*j4 .. 4*j4+3 ----
    const int j  = 4 * j4;
    int c0 = j / CTX_,  i0 = j - CTX_ * c0;
    int c1 = c0, i1 = i0 + 1; if (i1 == CTX_) { i1 = 0; c1++; }
    int c2 = c1, i2 = i1 + 1; if (i2 == CTX_) { i2 = 0; c2++; }
    int c3 = c2, i3 = i2 + 1; if (i3 == CTX_) { i3 = 0; c3++; }

    const float* p0 = &s[i0 * SPAD + c0];
    const float* p1 = &s[i1 * SPAD + c1];
    const float* p2 = &s[i2 * SPAD + c2];
    const float* p3 = &s[i3 * SPAD + c3];

    float4* outp = reinterpret_cast<float4*>(out)
                 + ((size_t)b * T_ + t0) * J4_ + j4;

    int tl = 0;

    // ---- Valid rows, 4 at a time: 16 independent LDS, then 4 STG.128 ----
#pragma unroll 1
    for (; tl + 4 <= v; tl += 4) {
        float r[16];
#pragma unroll
        for (int u = 0; u < 4; u++) {
            const int o = (tl + u) * SPAD;
            r[4*u + 0] = p0[o];
            r[4*u + 1] = p1[o];
            r[4*u + 2] = p2[o];
            r[4*u + 3] = p3[o];
        }
#pragma unroll
        for (int u = 0; u < 4; u++)
            __stcs(outp + (size_t)u * J4_,
                   make_float4(r[4*u], r[4*u + 1], r[4*u + 2], r[4*u + 3]));
        outp += (size_t)4 * J4_;
    }

    // ---- Remaining valid rows ----
#pragma unroll 1
    for (; tl < v; tl++) {
        const int o = tl * SPAD;
        __stcs(outp, make_float4(p0[o], p1[o], p2[o], p3[o]));
        outp += J4_;
    }

    // ---- Masked tail rows: streaming zero stores ----
    const float4 z = make_float4(0.f, 0.f, 0.f, 0.f);
#pragma unroll 1
    for (; tl + 4 <= n_stop; tl += 4) {
#pragma unroll
        for (int u = 0; u < 4; u++)
            __stcs(outp + (size_t)u * J4_, z);
        outp += (size_t)4 * J4_;
    }
#pragma unroll 1
    for (; tl < n_stop; tl++) {
        __stcs(outp, z);
        outp += J4_;
    }
}

extern "C" void kernel_launch(void* const* d_in, const int* in_sizes, int n_in,
                              void* d_out, int out_size)
{
    const float* x       = (const float*)d_in[0];
    const float* lengths = (const float*)d_in[1];
    float* out           = (float*)d_out;

    (void)in_sizes; (void)n_in; (void)out_size;

    dim3 grid(TILES * B_);   // 63 t-tiles x 32 batches, t-major heavy-first
    dim3 block(NTHR);
    context_window_kernel<<<grid, block>>>(x, lengths, out);
}

// round 16
// speedup vs baseline: 1.0428x; 1.0428x over previous
#include <cuda_runtime.h>
#include <math.h>

// ContextWindow: out[b, t, c*11 + i] = x[b, t+i-5, c] (zero pad in t),
// masked by t < round(2000 * lengths[b]).
// x: [32, 2000, 80] f32, lengths: [32] f32, out: [32, 2000, 880] f32.

#define B_    32
#define T_    2000
#define C_    80
#define C4_   20              // float4 per x row
#define CTX_  11
#define TT_   32              // t-rows per block
#define SROWS (TT_ + 10)      // 42 smem rows
#define SPAD  84              // 16B-aligned rows; bank key (20i+c)%32: ~2-way
#define SPAD4 21              // SPAD / 4
#define TILES 63              // ceil(2000/32)
#define J4_   (C_ * CTX_ / 4) // 220 float4 per output row
#define NTHR  256             // 8 warps: 2048 threads/SM at 8 blocks, faster fill

__global__ __launch_bounds__(NTHR) void context_window_kernel(
    const float* __restrict__ x,
    const float* __restrict__ lengths,
    float* __restrict__ out)
{
    __shared__ float s[SROWS * SPAD];

    const int blk = blockIdx.x;
    const int b   = blk & 31;            // t-major: heavy (low t0) blocks first
    const int t0  = (blk >> 5) * TT_;

    // jnp.round == round-half-to-even == rintf
    const int len_abs = (int)rintf((float)T_ * lengths[b]);
    const int n_stop  = min(TT_, T_ - t0);                   // rows that exist
    const int v       = min(max(len_abs - t0, 0), n_stop);   // non-zero rows

    const int j4 = threadIdx.x;

    // ---- Fast path: fully-masked tile -> streaming zero stores only ----
    if (v <= 0) {                                            // block-uniform
        if (j4 >= J4_) return;
        float4* outp = reinterpret_cast<float4*>(out)
                     + ((size_t)b * T_ + t0) * J4_ + j4;
        const float4 z = make_float4(0.f, 0.f, 0.f, 0.f);
        int tl = 0;
#pragma unroll 1
        for (; tl + 8 <= n_stop; tl += 8) {
#pragma unroll
            for (int u = 0; u < 8; u++)
                __stcs(outp + (size_t)u * J4_, z);
            outp += (size_t)8 * J4_;
        }
#pragma unroll 1
        for (; tl < n_stop; tl++) {
            __stcs(outp, z);
            outp += J4_;
        }
        return;
    }

    // ---- Fill smem tile + halo with float4 loads (all 256 threads) ----
    {
        const int n4 = (v + 10) * C4_;                       // <= 840 float4
        const float4* __restrict__ x4 =
            reinterpret_cast<const float4*>(x) + ((size_t)b * T_ + t0 - 5) * C4_;
        float4* __restrict__ s4 = reinterpret_cast<float4*>(s);

        const bool edge = (t0 < 5) || (t0 + SROWS - 5 > T_);

#pragma unroll 1
        for (int base = threadIdx.x; base < n4; base += 4 * NTHR) {
            float4 val[4];
#pragma unroll
            for (int u = 0; u < 4; u++) {
                const int idx = base + u * NTHR;
                int ok = (idx < n4);
                if (ok && edge) {
                    const int t = t0 + idx / C4_ - 5;
                    ok = (t >= 0 && t < T_);
                }
                val[u] = make_float4(0.f, 0.f, 0.f, 0.f);
                if (ok) val[u] = x4[idx];
            }
#pragma unroll
            for (int u = 0; u < 4; u++) {
                const int idx = base + u * NTHR;
                if (idx < n4) {
                    const int r  = idx / C4_;
                    const int c4 = idx - r * C4_;
                    s4[r * SPAD4 + c4] = val[u];
                }
            }
        }
    }
    __syncthreads();

    if (j4 >= J4_) return;

    // ---- Fixed per-thread (c,i) mapping for j = 4*j4 .. 4*j4+3 ----
    const int j  = 4 * j4;
    int c0 = j / CTX_,  i0 = j - CTX_ * c0;
    int c1 = c0, i1 = i0 + 1; if (i1 == CTX_) { i1 = 0; c1++; }
    int c2 = c1, i2 = i1 + 1; if (i2 == CTX_) { i2 = 0; c2++; }
    int c3 = c2, i3 = i2 + 1; if (i3 == CTX_) { i3 = 0; c3++; }

    const float* p0 = &s[i0 * SPAD + c0];
    const float* p1 = &s[i1 * SPAD + c1];
    const float* p2 = &s[i2 * SPAD + c2];
    const float* p3 = &s[i3 * SPAD + c3];

    float4* outp = reinterpret_cast<float4*>(out)
                 + ((size_t)b * T_ + t0) * J4_ + j4;

    int tl = 0;

    // ---- Valid rows, 4 at a time: 16 independent LDS, then 4 STG.128 ----
#pragma unroll 1
    for (; tl + 4 <= v; tl += 4) {
        float r[16];
#pragma unroll
        for (int u = 0; u < 4; u++) {
            const int o = (tl + u) * SPAD;
            r[4*u + 0] = p0[o];
            r[4*u + 1] = p1[o];
            r[4*u + 2] = p2[o];
            r[4*u + 3] = p3[o];
        }
#pragma unroll
        for (int u = 0; u < 4; u++)
            __stcs(outp + (size_t)u * J4_,
                   make_float4(r[4*u], r[4*u + 1], r[4*u + 2], r[4*u + 3]));
        outp += (size_t)4 * J4_;
    }

    // ---- Remaining valid rows ----
#pragma unroll 1
    for (; tl < v; tl++) {
        const int o = tl * SPAD;
        __stcs(outp, make_float4(p0[o], p1[o], p2[o], p3[o]));
        outp += J4_;
    }

    // ---- Masked tail rows: streaming zero stores ----
    const float4 z = make_float4(0.f, 0.f, 0.f, 0.f);
#pragma unroll 1
    for (; tl + 4 <= n_stop; tl += 4) {
#pragma unroll
        for (int u = 0; u < 4; u++)
            __stcs(outp + (size_t)u * J4_, z);
        outp += (size_t)4 * J4_;
    }
#pragma unroll 1
    for (; tl < n_stop; tl++) {
        __stcs(outp, z);
        outp += J4_;
    }
}

extern "C" void kernel_launch(void* const* d_in, const int* in_sizes, int n_in,
                              void* d_out, int out_size)
{
    const float* x       = (const float*)d_in[0];
    const float* lengths = (const float*)d_in[1];
    float* out           = (float*)d_out;

    (void)in_sizes; (void)n_in; (void)out_size;

    dim3 grid(TILES * B_);   // 63 t-tiles x 32 batches, t-major heavy-first
    dim3 block(NTHR);
    context_window_kernel<<<grid, block>>>(x, lengths, out);
}